// round 4
// baseline (speedup 1.0000x reference)
#include <cuda_runtime.h>
#include <cuda_fp16.h>
#include <math.h>
#include <stdint.h>

// ---------------- problem constants ----------------
#define NN      65536      // nodes
#define EE      1048576    // edges
#define BB      256        // graphs
#define LIN_INX 16384
#define LIN_OUTX 6400
#define EPSBN   1e-5f

// ---------------- scratch (device globals; allocation-free) ----------------
__device__ __align__(16) float g_P  [NN * 128];   // x @ Wl^T  (gather source)
__device__ __align__(16) float g_pre[NN * 128];   // x @ Wr^T + b, then += agg*inv
__device__ __align__(16) float g_bufA[NN * 128];  // layer outputs (ping)
__device__ __align__(16) float g_bufB[NN * 128];  // layer outputs (pong)
__device__ __align__(16) float g_Y1 [BB * LIN_OUTX];
__device__ __align__(16) float g_mu [BB * LIN_OUTX];  // also split-K partial 0
__device__ __align__(16) float g_sg [BB * LIN_OUTX];  // also split-K partial 1
__device__ float g_inv[NN];
__device__ int   g_cnt[NN];
__device__ int   g_off[NN + 1];
__device__ int   g_cursor[NN];
__device__ int   g_csr[EE];
__device__ float g_stats[256];   // [0:128) sum, [128:256) sumsq
__device__ float g_scale[128];
__device__ float g_shift[128];

// ---------------- graph preprocessing (once per call) ----------------
__global__ void count_edges(const int* __restrict__ dst) {
    int e = blockIdx.x * blockDim.x + threadIdx.x;
    if (e < EE) atomicAdd(&g_cnt[__ldg(dst + e)], 1);
}

// single block, 1024 threads: exclusive scan of 65536 counts -> offsets + cursor + inv
__global__ void __launch_bounds__(1024) scan_offsets() {
    __shared__ int part[1024];
    int t = threadIdx.x;
    int base = t * 64;
    int s = 0;
    for (int i = 0; i < 64; i++) s += g_cnt[base + i];
    part[t] = s;
    __syncthreads();
    for (int d = 1; d < 1024; d <<= 1) {
        int u = (t >= d) ? part[t - d] : 0;
        __syncthreads();
        part[t] += u;
        __syncthreads();
    }
    int run = part[t] - s;               // exclusive prefix of this 64-chunk
    for (int i = 0; i < 64; i++) {
        int c = g_cnt[base + i];
        g_off[base + i] = run;
        g_cursor[base + i] = run;
        g_inv[base + i] = 1.0f / fmaxf((float)c, 1.0f);
        run += c;
    }
    if (t == 1023) g_off[NN] = run;
}

__global__ void csr_fill(const int* __restrict__ src, const int* __restrict__ dst) {
    int e = blockIdx.x * blockDim.x + threadIdx.x;
    if (e < EE) {
        int d = __ldg(dst + e);
        int pos = atomicAdd(&g_cursor[d], 1);
        g_csr[pos] = __ldg(src + e);
    }
}

// ---------------- fused gather-aggregate + combine + BN stats ----------------
// H=128: one warp per node, float4 per lane. Block = 8 warps x 8 node-iterations = 64 nodes.
__global__ void __launch_bounds__(256) agg_combine128(const float* __restrict__ P,
                                                      float* __restrict__ pre) {
    __shared__ float ssum[128], ssq[128];
    int t = threadIdx.x;
    if (t < 128) { ssum[t] = 0.f; ssq[t] = 0.f; }
    __syncthreads();
    int warp = t >> 5, lane = t & 31;
    float ls0 = 0, ls1 = 0, ls2 = 0, ls3 = 0;
    float lq0 = 0, lq1 = 0, lq2 = 0, lq3 = 0;
    int nbase = blockIdx.x * 64;
    const float* col = P + lane * 4;
#pragma unroll 1
    for (int it = 0; it < 8; it++) {
        int node = nbase + it * 8 + warp;
        int beg = g_off[node], end = g_off[node + 1];
        float4 a0 = {0, 0, 0, 0}, a1 = {0, 0, 0, 0};
        int e = beg;
        for (; e + 2 <= end; e += 2) {
            int s0 = __ldg(&g_csr[e]);
            int s1 = __ldg(&g_csr[e + 1]);
            float4 v0 = *(const float4*)(col + (size_t)s0 * 128);
            float4 v1 = *(const float4*)(col + (size_t)s1 * 128);
            a0.x += v0.x; a0.y += v0.y; a0.z += v0.z; a0.w += v0.w;
            a1.x += v1.x; a1.y += v1.y; a1.z += v1.z; a1.w += v1.w;
        }
        if (e < end) {
            int s0 = __ldg(&g_csr[e]);
            float4 v0 = *(const float4*)(col + (size_t)s0 * 128);
            a0.x += v0.x; a0.y += v0.y; a0.z += v0.z; a0.w += v0.w;
        }
        float inv = g_inv[node];
        float4 pv = *(const float4*)(pre + (size_t)node * 128 + lane * 4);
        float4 v;
        v.x = fmaf(a0.x + a1.x, inv, pv.x);
        v.y = fmaf(a0.y + a1.y, inv, pv.y);
        v.z = fmaf(a0.z + a1.z, inv, pv.z);
        v.w = fmaf(a0.w + a1.w, inv, pv.w);
        *(float4*)(pre + (size_t)node * 128 + lane * 4) = v;
        ls0 += v.x; ls1 += v.y; ls2 += v.z; ls3 += v.w;
        lq0 += v.x * v.x; lq1 += v.y * v.y; lq2 += v.z * v.z; lq3 += v.w * v.w;
    }
    atomicAdd(&ssum[lane * 4 + 0], ls0); atomicAdd(&ssum[lane * 4 + 1], ls1);
    atomicAdd(&ssum[lane * 4 + 2], ls2); atomicAdd(&ssum[lane * 4 + 3], ls3);
    atomicAdd(&ssq [lane * 4 + 0], lq0); atomicAdd(&ssq [lane * 4 + 1], lq1);
    atomicAdd(&ssq [lane * 4 + 2], lq2); atomicAdd(&ssq [lane * 4 + 3], lq3);
    __syncthreads();
    if (t < 128) {
        atomicAdd(&g_stats[t], ssum[t]);
        atomicAdd(&g_stats[128 + t], ssq[t]);
    }
}

// H=64: one warp per node, float2 per lane.
__global__ void __launch_bounds__(256) agg_combine64(const float* __restrict__ P,
                                                     float* __restrict__ pre) {
    __shared__ float ssum[64], ssq[64];
    int t = threadIdx.x;
    if (t < 64) { ssum[t] = 0.f; ssq[t] = 0.f; }
    __syncthreads();
    int warp = t >> 5, lane = t & 31;
    float ls0 = 0, ls1 = 0, lq0 = 0, lq1 = 0;
    int nbase = blockIdx.x * 64;
    const float* col = P + lane * 2;
#pragma unroll 1
    for (int it = 0; it < 8; it++) {
        int node = nbase + it * 8 + warp;
        int beg = g_off[node], end = g_off[node + 1];
        float2 a0 = {0, 0}, a1 = {0, 0};
        int e = beg;
        for (; e + 2 <= end; e += 2) {
            int s0 = __ldg(&g_csr[e]);
            int s1 = __ldg(&g_csr[e + 1]);
            float2 v0 = *(const float2*)(col + (size_t)s0 * 64);
            float2 v1 = *(const float2*)(col + (size_t)s1 * 64);
            a0.x += v0.x; a0.y += v0.y;
            a1.x += v1.x; a1.y += v1.y;
        }
        if (e < end) {
            int s0 = __ldg(&g_csr[e]);
            float2 v0 = *(const float2*)(col + (size_t)s0 * 64);
            a0.x += v0.x; a0.y += v0.y;
        }
        float inv = g_inv[node];
        float2 pv = *(const float2*)(pre + (size_t)node * 64 + lane * 2);
        float2 v;
        v.x = fmaf(a0.x + a1.x, inv, pv.x);
        v.y = fmaf(a0.y + a1.y, inv, pv.y);
        *(float2*)(pre + (size_t)node * 64 + lane * 2) = v;
        ls0 += v.x; ls1 += v.y;
        lq0 += v.x * v.x; lq1 += v.y * v.y;
    }
    atomicAdd(&ssum[lane * 2 + 0], ls0); atomicAdd(&ssum[lane * 2 + 1], ls1);
    atomicAdd(&ssq [lane * 2 + 0], lq0); atomicAdd(&ssq [lane * 2 + 1], lq1);
    __syncthreads();
    if (t < 64) {
        atomicAdd(&g_stats[t], ssum[t]);
        atomicAdd(&g_stats[128 + t], ssq[t]);
    }
}

template<int H>
__global__ void finalize_stats(const float* __restrict__ gamma, const float* __restrict__ beta) {
    int c = threadIdx.x;
    if (c < H) {
        float m   = g_stats[c] * (1.0f / NN);
        float var = g_stats[128 + c] * (1.0f / NN) - m * m;
        float sc  = gamma[c] * rsqrtf(var + EPSBN);
        g_scale[c] = sc;
        g_shift[c] = beta[c] - m * sc;
    }
}

template<int H>
__global__ void bn_relu_kernel(const float* __restrict__ pre, float* __restrict__ out) {
    unsigned idx = blockIdx.x * blockDim.x + threadIdx.x;   // total = NN*H/4 (exact)
    float4 v = *(const float4*)(pre + (size_t)idx * 4);
    int c = (idx * 4) & (H - 1);
    v.x = fmaxf(fmaf(v.x, g_scale[c + 0], g_shift[c + 0]), 0.f);
    v.y = fmaxf(fmaf(v.y, g_scale[c + 1], g_shift[c + 1]), 0.f);
    v.z = fmaxf(fmaf(v.z, g_scale[c + 2], g_shift[c + 2]), 0.f);
    v.w = fmaxf(fmaf(v.w, g_scale[c + 3], g_shift[c + 3]), 0.f);
    *(float4*)(out + (size_t)idx * 4) = v;
}

// final head batchnorm over 256 rows, one thread per column
__global__ void head_bn(const float* __restrict__ P, const float* __restrict__ gamma,
                        const float* __restrict__ beta, float* __restrict__ out) {
    int c = blockIdx.x * blockDim.x + threadIdx.x;
    if (c >= LIN_OUTX) return;
    float s = 0.f, s2 = 0.f;
    for (int r = 0; r < BB; r++) {
        float v = P[(size_t)r * LIN_OUTX + c];
        s += v; s2 += v * v;
    }
    float m   = s * (1.0f / BB);
    float var = s2 * (1.0f / BB) - m * m;
    float sc  = gamma[c] * rsqrtf(var + EPSBN);
    float shf = beta[c] - m * sc;
    for (int r = 0; r < BB; r++)
        out[(size_t)r * LIN_OUTX + c] = P[(size_t)r * LIN_OUTX + c] * sc + shf;
}

// split-K combine: Y = tanh(p0 + p1 + bias)
__global__ void combine_tanh(const float* __restrict__ p0, const float* __restrict__ p1,
                             const float* __restrict__ bias, float* __restrict__ Y) {
    unsigned i = blockIdx.x * blockDim.x + threadIdx.x;   // total = BB*LIN_OUTX/4
    float4 a = *(const float4*)(p0 + (size_t)i * 4);
    float4 b = *(const float4*)(p1 + (size_t)i * 4);
    int col = (i * 4) % LIN_OUTX;
    float4 bs = *(const float4*)(bias + col);
    float4 o;
    o.x = tanhf(a.x + b.x + bs.x);
    o.y = tanhf(a.y + b.y + bs.y);
    o.z = tanhf(a.z + b.z + bs.z);
    o.w = tanhf(a.w + b.w + bs.w);
    *(float4*)(Y + (size_t)i * 4) = o;
}

// ---------------- fp32 SGEMM (layer GEMMs, K=128) ----------------
template<int ACT>
__global__ void __launch_bounds__(256) sgemm_nt(
    const float* __restrict__ A, const float* __restrict__ W,
    const float* __restrict__ bias, float* __restrict__ C,
    int M, int N, int K)
{
    __shared__ float As[16][132];
    __shared__ float Ws[16][68];
    const int tid = threadIdx.x;
    const int m0 = blockIdx.y * 128;
    const int n0 = blockIdx.x * 64;
    const int tx = tid & 15;
    const int ty = tid >> 4;
    const int lr = tid >> 2;       // 0..63
    const int lq = (tid & 3) * 4;  // 0,4,8,12

    const float* Ag0 = A + (size_t)(m0 + lr) * K + lq;
    const float* Ag1 = A + (size_t)(m0 + 64 + lr) * K + lq;
    const float* Wg  = W + (size_t)(n0 + lr) * K + lq;

    float acc[8][4];
#pragma unroll
    for (int i = 0; i < 8; i++)
#pragma unroll
        for (int j = 0; j < 4; j++) acc[i][j] = 0.f;

    float4 a0 = *(const float4*)(Ag0);
    float4 a1 = *(const float4*)(Ag1);
    float4 w0 = *(const float4*)(Wg);

    for (int kt = 0; kt < K; kt += 16) {
        __syncthreads();
        As[lq + 0][lr]      = a0.x; As[lq + 1][lr]      = a0.y;
        As[lq + 2][lr]      = a0.z; As[lq + 3][lr]      = a0.w;
        As[lq + 0][lr + 64] = a1.x; As[lq + 1][lr + 64] = a1.y;
        As[lq + 2][lr + 64] = a1.z; As[lq + 3][lr + 64] = a1.w;
        Ws[lq + 0][lr] = w0.x; Ws[lq + 1][lr] = w0.y;
        Ws[lq + 2][lr] = w0.z; Ws[lq + 3][lr] = w0.w;
        __syncthreads();

        int kn = kt + 16;
        if (kn < K) {
            a0 = *(const float4*)(Ag0 + kn);
            a1 = *(const float4*)(Ag1 + kn);
            w0 = *(const float4*)(Wg  + kn);
        }

#pragma unroll
        for (int k = 0; k < 16; k++) {
            float4 aa0 = *(const float4*)&As[k][ty * 8];
            float4 aa1 = *(const float4*)&As[k][ty * 8 + 4];
            float4 bb  = *(const float4*)&Ws[k][tx * 4];
            float a[8] = {aa0.x, aa0.y, aa0.z, aa0.w, aa1.x, aa1.y, aa1.z, aa1.w};
            float b[4] = {bb.x, bb.y, bb.z, bb.w};
#pragma unroll
            for (int i = 0; i < 8; i++)
#pragma unroll
                for (int j = 0; j < 4; j++)
                    acc[i][j] = fmaf(a[i], b[j], acc[i][j]);
        }
    }

    float4 bv = make_float4(0.f, 0.f, 0.f, 0.f);
    if (bias) bv = *(const float4*)(bias + n0 + tx * 4);
#pragma unroll
    for (int i = 0; i < 8; i++) {
        float4 o;
        o.x = acc[i][0] + bv.x; o.y = acc[i][1] + bv.y;
        o.z = acc[i][2] + bv.z; o.w = acc[i][3] + bv.w;
        if (ACT == 2) { o.x = tanhf(o.x); o.y = tanhf(o.y); o.z = tanhf(o.z); o.w = tanhf(o.w); }
        *(float4*)(C + (size_t)(m0 + ty * 8 + i) * N + n0 + tx * 4) = o;
    }
}

// ---------------- fp16 tensor-core GEMM (head GEMMs) ----------------
__device__ __forceinline__ void mma_f16(float c[4], const uint32_t a[4], const uint32_t b[2]) {
    asm("mma.sync.aligned.m16n8k16.row.col.f32.f16.f16.f32 "
        "{%0,%1,%2,%3},{%4,%5,%6,%7},{%8,%9},{%0,%1,%2,%3};"
        : "+f"(c[0]), "+f"(c[1]), "+f"(c[2]), "+f"(c[3])
        : "r"(a[0]), "r"(a[1]), "r"(a[2]), "r"(a[3]), "r"(b[0]), "r"(b[1]));
}

#define TPITCH 20
#define ABUF   (256 * TPITCH)
#define WBASE  (2 * ABUF)
#define WBUF   (64 * TPITCH)
#define HGEMM_SMEM_BYTES ((WBASE + 2 * WBUF) * 4)   // 51200

__device__ __forceinline__ uint32_t pack_h2(float x, float y) {
    __half2 h = __float22half2_rn(make_float2(x, y));
    return *(uint32_t*)&h;
}

// C[256,N] = act(A[256,Kloop]@W^T + bias). lda/ldw are row pitches (support split-K).
__device__ __forceinline__ void gemm_f16_core(
    const float* __restrict__ A, int lda, const float* __restrict__ W, int ldw,
    const float* __restrict__ bias, float* __restrict__ C,
    int N, int Kloop, int n0, int act, uint32_t* sh)
{
    const int tid  = threadIdx.x;
    const int lane = tid & 31;
    const int wid  = tid >> 5;
    const int mw   = wid & 3;
    const int nw   = wid >> 2;
    const int gid  = lane >> 2;
    const int tig  = lane & 3;

    const int arow = tid >> 2;
    const int ac4  = tid & 3;

    const float* Ag = A + (size_t)arow * lda + ac4 * 4;
    const float* Wg = W + (size_t)(n0 + arow) * ldw + ac4 * 4;

    float acc[4][4][4];
#pragma unroll
    for (int i = 0; i < 4; i++)
#pragma unroll
        for (int j = 0; j < 4; j++)
#pragma unroll
            for (int q = 0; q < 4; q++) acc[i][j][q] = 0.f;

    float4 av[4][2], wv[2];

#pragma unroll
    for (int t = 0; t < 4; t++) {
        av[t][0] = *(const float4*)(Ag + (size_t)(64 * t) * lda);
        av[t][1] = *(const float4*)(Ag + (size_t)(64 * t) * lda + 16);
    }
    wv[0] = *(const float4*)(Wg);
    wv[1] = *(const float4*)(Wg + 16);

    auto store_tile = [&](int buf) {
        uint32_t* ap = sh + buf * ABUF;
        uint32_t* wp = sh + WBASE + buf * WBUF;
#pragma unroll
        for (int t = 0; t < 4; t++) {
            uint32_t* d = ap + (arow + 64 * t) * TPITCH;
            *(uint2*)(d + ac4 * 2)     = make_uint2(pack_h2(av[t][0].x, av[t][0].y),
                                                    pack_h2(av[t][0].z, av[t][0].w));
            *(uint2*)(d + 8 + ac4 * 2) = make_uint2(pack_h2(av[t][1].x, av[t][1].y),
                                                    pack_h2(av[t][1].z, av[t][1].w));
        }
        uint32_t* d = wp + arow * TPITCH;
        *(uint2*)(d + ac4 * 2)     = make_uint2(pack_h2(wv[0].x, wv[0].y),
                                                pack_h2(wv[0].z, wv[0].w));
        *(uint2*)(d + 8 + ac4 * 2) = make_uint2(pack_h2(wv[1].x, wv[1].y),
                                                pack_h2(wv[1].z, wv[1].w));
    };

    store_tile(0);
    __syncthreads();

    const int ntiles = Kloop / 32;
    for (int it = 0; it < ntiles; it++) {
        int buf = it & 1;
        if (it + 1 < ntiles) {
            int kn = (it + 1) * 32;
#pragma unroll
            for (int t = 0; t < 4; t++) {
                av[t][0] = *(const float4*)(Ag + (size_t)(64 * t) * lda + kn);
                av[t][1] = *(const float4*)(Ag + (size_t)(64 * t) * lda + kn + 16);
            }
            wv[0] = *(const float4*)(Wg + kn);
            wv[1] = *(const float4*)(Wg + kn + 16);
        }

        const uint32_t* ap = sh + buf * ABUF;
        const uint32_t* wp = sh + WBASE + buf * WBUF;

#pragma unroll
        for (int s = 0; s < 2; s++) {
            const int k0 = s * 8;
            uint32_t afr[4][4], bfr[4][2];
#pragma unroll
            for (int i = 0; i < 4; i++) {
                int r = mw * 64 + i * 16 + gid;
                afr[i][0] = ap[(r    ) * TPITCH + k0 + tig];
                afr[i][1] = ap[(r + 8) * TPITCH + k0 + tig];
                afr[i][2] = ap[(r    ) * TPITCH + k0 + tig + 4];
                afr[i][3] = ap[(r + 8) * TPITCH + k0 + tig + 4];
            }
#pragma unroll
            for (int j = 0; j < 4; j++) {
                int r = nw * 32 + j * 8 + gid;
                bfr[j][0] = wp[r * TPITCH + k0 + tig];
                bfr[j][1] = wp[r * TPITCH + k0 + tig + 4];
            }
#pragma unroll
            for (int i = 0; i < 4; i++)
#pragma unroll
                for (int j = 0; j < 4; j++)
                    mma_f16(acc[i][j], afr[i], bfr[j]);
        }

        if (it + 1 < ntiles) store_tile(buf ^ 1);
        __syncthreads();
    }

#pragma unroll
    for (int i = 0; i < 4; i++) {
        int mrow = mw * 64 + i * 16 + gid;
#pragma unroll
        for (int j = 0; j < 4; j++) {
            int ncol = n0 + nw * 32 + j * 8 + 2 * tig;
            float bx = bias ? bias[ncol] : 0.f;
            float by = bias ? bias[ncol + 1] : 0.f;
            float o0 = acc[i][j][0] + bx, o1 = acc[i][j][1] + by;
            float o2 = acc[i][j][2] + bx, o3 = acc[i][j][3] + by;
            if (act == 2) { o0 = tanhf(o0); o1 = tanhf(o1); o2 = tanhf(o2); o3 = tanhf(o3); }
            *(float2*)(C + (size_t)mrow * N + ncol)       = make_float2(o0, o1);
            *(float2*)(C + (size_t)(mrow + 8) * N + ncol) = make_float2(o2, o3);
        }
    }
}

// Wlin split-K=2: grid.x = 2 * (LIN_OUTX/64); partials to P0/P1 (no bias/act)
__global__ void __launch_bounds__(256, 1) gemm_f16_wlin(
    const float* __restrict__ A, const float* __restrict__ W,
    float* __restrict__ P0, float* __restrict__ P1)
{
    extern __shared__ uint32_t sh[];
    const int nblk = LIN_OUTX / 64;
    int bx = blockIdx.x;
    if (bx < nblk)
        gemm_f16_core(A, LIN_INX, W, LIN_INX, nullptr, P0,
                      LIN_OUTX, LIN_INX / 2, bx * 64, 0, sh);
    else
        gemm_f16_core(A + LIN_INX / 2, LIN_INX, W + LIN_INX / 2, LIN_INX, nullptr, P1,
                      LIN_OUTX, LIN_INX / 2, (bx - nblk) * 64, 0, sh);
}

// fused mu+sigma: same A, two weight sets; grid.x = 2 * (N/64)
__global__ void __launch_bounds__(256, 1) gemm_f16_dual(
    const float* __restrict__ A,
    const float* __restrict__ W0, const float* __restrict__ b0, float* __restrict__ C0,
    const float* __restrict__ W1, const float* __restrict__ b1, float* __restrict__ C1,
    int N, int K)
{
    extern __shared__ uint32_t sh[];
    int nblk = N / 64;
    int bx = blockIdx.x;
    if (bx < nblk)
        gemm_f16_core(A, K, W0, K, b0, C0, N, K, bx * 64, 0, sh);
    else
        gemm_f16_core(A, K, W1, K, b1, C1, N, K, (bx - nblk) * 64, 0, sh);
}

// ---------------- host orchestration ----------------
static void* symaddr(const void* sym) {
    void* p = nullptr;
    cudaGetSymbolAddress(&p, sym);
    return p;
}

extern "C" void kernel_launch(void* const* d_in, const int* in_sizes, int n_in,
                              void* d_out, int out_size)
{
    const float* x    = (const float*)d_in[0];
    const int*   ei   = (const int*)  d_in[1];
    const int*   srcI = ei;
    const int*   dstI = ei + EE;
    const float *W1l = (const float*)d_in[3],  *b1l = (const float*)d_in[4],  *W1r = (const float*)d_in[5];
    const float *gm1 = (const float*)d_in[6],  *be1 = (const float*)d_in[7];
    const float *W2l = (const float*)d_in[8],  *b2l = (const float*)d_in[9],  *W2r = (const float*)d_in[10];
    const float *gm2 = (const float*)d_in[11], *be2 = (const float*)d_in[12];
    const float *W3l = (const float*)d_in[13], *b3l = (const float*)d_in[14], *W3r = (const float*)d_in[15];
    const float *gm3 = (const float*)d_in[16], *be3 = (const float*)d_in[17];
    const float *Wlin = (const float*)d_in[18], *blin = (const float*)d_in[19];
    const float *Wmu  = (const float*)d_in[20], *bmu  = (const float*)d_in[21];
    const float *Wsig = (const float*)d_in[22], *bsig = (const float*)d_in[23];
    const float *gfx  = (const float*)d_in[24], *bfx  = (const float*)d_in[25];
    const float *gfs  = (const float*)d_in[26], *bfs  = (const float*)d_in[27];
    float* out = (float*)d_out;

    float* pP    = (float*)symaddr(g_P);
    float* pPre  = (float*)symaddr(g_pre);
    float* pA    = (float*)symaddr(g_bufA);
    float* pB    = (float*)symaddr(g_bufB);
    float* pY1   = (float*)symaddr(g_Y1);
    float* pMu   = (float*)symaddr(g_mu);
    float* pSg   = (float*)symaddr(g_sg);
    int*   pCnt  = (int*)  symaddr(g_cnt);
    float* pStat = (float*)symaddr(g_stats);

    static bool attr_done = false;
    if (!attr_done) {
        cudaFuncSetAttribute(gemm_f16_wlin, cudaFuncAttributeMaxDynamicSharedMemorySize, HGEMM_SMEM_BYTES);
        cudaFuncSetAttribute(gemm_f16_dual, cudaFuncAttributeMaxDynamicSharedMemorySize, HGEMM_SMEM_BYTES);
        attr_done = true;
    }

    // ---- graph preprocessing: counts -> offsets -> CSR ----
    cudaMemsetAsync(pCnt, 0, NN * sizeof(int));
    count_edges<<<EE / 256, 256>>>(dstI);
    scan_offsets<<<1, 1024>>>();
    csr_fill<<<EE / 256, 256>>>(srcI, dstI);

    // ---- layer 1 ----
    {
        dim3 gl(128 / 64, NN / 128);
        sgemm_nt<0><<<gl, 256>>>(x, W1l, nullptr, pP,   NN, 128, 128);
        sgemm_nt<0><<<gl, 256>>>(x, W1r, b1l,     pPre, NN, 128, 128);
        cudaMemsetAsync(pStat, 0, 256 * sizeof(float));
        agg_combine128<<<NN / 64, 256>>>(pP, pPre);
        finalize_stats<128><<<1, 128>>>(gm1, be1);
        bn_relu_kernel<128><<<NN * 128 / 4 / 256, 256>>>(pPre, pA);
    }
    // ---- layer 2 ----
    {
        dim3 gl(128 / 64, NN / 128);
        sgemm_nt<0><<<gl, 256>>>(pA, W2l, nullptr, pP,   NN, 128, 128);
        sgemm_nt<0><<<gl, 256>>>(pA, W2r, b2l,     pPre, NN, 128, 128);
        cudaMemsetAsync(pStat, 0, 256 * sizeof(float));
        agg_combine128<<<NN / 64, 256>>>(pP, pPre);
        finalize_stats<128><<<1, 128>>>(gm2, be2);
        bn_relu_kernel<128><<<NN * 128 / 4 / 256, 256>>>(pPre, pB);
    }
    // ---- layer 3 (H=64) ----
    {
        dim3 gl(64 / 64, NN / 128);
        sgemm_nt<0><<<gl, 256>>>(pB, W3l, nullptr, pP,   NN, 64, 128);
        sgemm_nt<0><<<gl, 256>>>(pB, W3r, b3l,     pPre, NN, 64, 128);
        cudaMemsetAsync(pStat, 0, 256 * sizeof(float));
        agg_combine64<<<NN / 64, 256>>>(pP, pPre);
        finalize_stats<64><<<1, 64>>>(gm3, be3);
        bn_relu_kernel<64><<<NN * 64 / 4 / 256, 256>>>(pPre, pA);
    }

    // ---- head: bufA viewed as [256, 16384], fp16 tensor cores ----
    {
        gemm_f16_wlin<<<dim3(2 * LIN_OUTX / 64, 1), 256, HGEMM_SMEM_BYTES>>>(pA, Wlin, pMu, pSg);
        combine_tanh<<<BB * LIN_OUTX / 4 / 256, 256>>>(pMu, pSg, blin, pY1);
        gemm_f16_dual<<<dim3(2 * LIN_OUTX / 64, 1), 256, HGEMM_SMEM_BYTES>>>(
            pY1, Wmu, bmu, pMu, Wsig, bsig, pSg, LIN_OUTX, LIN_OUTX);
        head_bn<<<(LIN_OUTX + 255) / 256, 256>>>(pMu, gfx, bfx, out);
        head_bn<<<(LIN_OUTX + 255) / 256, 256>>>(pSg, gfs, bfs, out + (size_t)BB * LIN_OUTX);
    }
}